// round 4
// baseline (speedup 1.0000x reference)
#include <cuda_runtime.h>
#include <math.h>

// Problem constants
#define C_DIM   1024
#define BATCH   8
#define SEQ     512
#define HEADS   16
#define HD      64
#define RANK    32
#define TOKENS  (BATCH*SEQ)     // 4096
#define N3C     (3*C_DIM)       // 3072
#define MASK_N  (BATCH*3*SEQ)   // 12288

// ---------------- scratch (static device memory; no allocs) ----------------
__device__ float g_qkv_eff [C_DIM*N3C];
__device__ float g_fc1_eff [C_DIM*C_DIM];
__device__ float g_fc2_eff [C_DIM*C_DIM];
__device__ float g_proj_eff[C_DIM*C_DIM];
__device__ float g_qkv     [TOKENS*N3C];
__device__ float g_xo      [TOKENS*C_DIM];
__device__ float g_h       [TOKENS*C_DIM];
__device__ float g_y       [TOKENS*C_DIM];
__device__ unsigned char g_mask[MASK_N];

// ---------------- mask canonicalization (dtype-robust) ---------------------
// The bool mask may be stored as uint8, int32, or float32. Detect from the
// bit patterns (values are only 0/1) and convert to canonical uint8.
//  - any word == 0x3F800000 -> float32 (impossible for 0/1-valued u8/i32 data)
//  - else any word > 1      -> uint8   (packed 0/1 bytes: 256, 0x0101.., etc.)
//  - else                   -> int32
__global__ void mask_canon_kernel(const unsigned int* __restrict__ m,
                                  unsigned char* __restrict__ out)
{
    __shared__ int flagF, flagBig;
    if (threadIdx.x == 0) { flagF = 0; flagBig = 0; }
    __syncthreads();
    for (int i = threadIdx.x; i < MASK_N / 4; i += blockDim.x) {
        unsigned int w = m[i];
        if (w == 0x3F800000u) atomicOr(&flagF, 1);
        else if (w > 1u)      atomicOr(&flagBig, 1);
    }
    __syncthreads();
    const int mode = flagF ? 2 : (flagBig ? 0 : 1);  // 2=f32, 0=u8, 1=i32
    const unsigned char* mu = (const unsigned char*)m;
    const float*         mf = (const float*)m;
    const int*           mi = (const int*)m;
    for (int i = threadIdx.x; i < MASK_N; i += blockDim.x) {
        unsigned char v;
        if (mode == 0)      v = mu[i] ? 1 : 0;
        else if (mode == 1) v = mi[i] ? 1 : 0;
        else                v = (mf[i] != 0.f) ? 1 : 0;
        out[i] = v;
    }
}

// ---------------- LoRA weight folding: out = W + la @ lb -------------------
__global__ __launch_bounds__(256)
void lora_eff_kernel(const float* __restrict__ W,
                     const float* __restrict__ la,
                     const float* __restrict__ lb,
                     float* __restrict__ out, int N)
{
    int n = blockIdx.x * 256 + threadIdx.x;
    int k = blockIdx.y;
    float acc = W[(size_t)k * N + n];
#pragma unroll
    for (int r = 0; r < RANK; r++)
        acc += la[k * RANK + r] * lb[(size_t)r * N + n];
    out[(size_t)k * N + n] = acc;
}

// ---------------- fp32 SGEMM: C = A[M,K] @ B[K,N] (+bias)(+gelu)(+res) -----
#define BM 128
#define BN 128
#define BK 8

__device__ __forceinline__ float gelu_exact(float v)
{
    return 0.5f * v * (1.0f + erff(v * 0.70710678118654752f));
}

__global__ __launch_bounds__(256)
void sgemm_kernel(const float* __restrict__ A, const float* __restrict__ B,
                  const float* __restrict__ bias, const float* __restrict__ res,
                  float* __restrict__ C, int M, int N, int K, int do_gelu)
{
    __shared__ float As[2][BK][BM];
    __shared__ float Bs[2][BK][BN];

    const int tid = threadIdx.x;
    const int tx = tid & 15;
    const int ty = tid >> 4;
    const int row0 = blockIdx.y * BM;
    const int col0 = blockIdx.x * BN;

    const int a_row = tid >> 1;          // 0..127
    const int a_col = (tid & 1) * 4;     // 0 or 4
    const int b_row = tid >> 5;          // 0..7
    const int b_col = (tid & 31) * 4;    // 0..124

    const float* Aptr = A + (size_t)(row0 + a_row) * K + a_col;
    const float* Bptr = B + (size_t)b_row * N + col0 + b_col;

    float acc[8][8];
#pragma unroll
    for (int i = 0; i < 8; i++)
#pragma unroll
        for (int j = 0; j < 8; j++) acc[i][j] = 0.f;

    // preload tile 0 into buffer 0
    {
        float4 av = *(const float4*)(Aptr);
        As[0][a_col + 0][a_row] = av.x;
        As[0][a_col + 1][a_row] = av.y;
        As[0][a_col + 2][a_row] = av.z;
        As[0][a_col + 3][a_row] = av.w;
        float4 bv = *(const float4*)(Bptr);
        *(float4*)&Bs[0][b_row][b_col] = bv;
    }
    __syncthreads();

    int buf = 0;
    for (int k0 = 0; k0 < K; k0 += BK) {
        const bool has_next = (k0 + BK) < K;
        float4 av_n, bv_n;
        if (has_next) {
            av_n = *(const float4*)(Aptr + (k0 + BK));
            bv_n = *(const float4*)(Bptr + (size_t)(k0 + BK) * N);
        }

#pragma unroll
        for (int kk = 0; kk < BK; kk++) {
            float4 a0 = *(const float4*)&As[buf][kk][ty * 4];
            float4 a1 = *(const float4*)&As[buf][kk][64 + ty * 4];
            float4 b0 = *(const float4*)&Bs[buf][kk][tx * 4];
            float4 b1 = *(const float4*)&Bs[buf][kk][64 + tx * 4];
            float a_[8] = {a0.x,a0.y,a0.z,a0.w,a1.x,a1.y,a1.z,a1.w};
            float b_[8] = {b0.x,b0.y,b0.z,b0.w,b1.x,b1.y,b1.z,b1.w};
#pragma unroll
            for (int i = 0; i < 8; i++)
#pragma unroll
                for (int j = 0; j < 8; j++)
                    acc[i][j] = fmaf(a_[i], b_[j], acc[i][j]);
        }

        if (has_next) {
            int nb = buf ^ 1;
            As[nb][a_col + 0][a_row] = av_n.x;
            As[nb][a_col + 1][a_row] = av_n.y;
            As[nb][a_col + 2][a_row] = av_n.z;
            As[nb][a_col + 3][a_row] = av_n.w;
            *(float4*)&Bs[nb][b_row][b_col] = bv_n;
            __syncthreads();
            buf = nb;
        }
    }

    // epilogue: bias -> gelu -> residual
#pragma unroll
    for (int i = 0; i < 8; i++) {
        int r = row0 + ((i < 4) ? (ty * 4 + i) : (64 + ty * 4 + i - 4));
#pragma unroll
        for (int j = 0; j < 8; j++) {
            int c = col0 + ((j < 4) ? (tx * 4 + j) : (64 + tx * 4 + j - 4));
            float v = acc[i][j];
            if (bias) v += bias[c];
            if (do_gelu) v = gelu_exact(v);
            if (res) v += res[(size_t)r * N + c];
            C[(size_t)r * N + c] = v;
        }
    }
}

// ---------------- fused masked flash attention -----------------------------
__global__ __launch_bounds__(256)
void attention_kernel(const float* __restrict__ qkv,
                      const unsigned char* __restrict__ mask,
                      float* __restrict__ xo)
{
    __shared__ float Qst[HD * 64];    // [d][q]
    __shared__ float KPs[64 * 64];    // Kst [d][k] -> Ps [q][k]
    __shared__ float Vs [64 * 64];    // [k][d]

    const int qt = blockIdx.x;        // 0..7
    const int h  = blockIdx.y;        // 0..15
    const int b  = blockIdx.z;        // 0..7
    const int tid = threadIdx.x;
    const int tx = tid & 15;
    const int ty = tid >> 4;
    const float scale = 0.125f;       // 64^-0.5

    // load Q tile (transposed + scaled)
    {
        const int d4 = (tid & 15) * 4;
        const int r0 = tid >> 4;
#pragma unroll
        for (int p = 0; p < 4; p++) {
            int q = r0 + p * 16;
            float4 v = *(const float4*)(qkv + (size_t)(b * SEQ + qt * 64 + q) * N3C + h * HD + d4);
            Qst[(d4 + 0) * 64 + q] = v.x * scale;
            Qst[(d4 + 1) * 64 + q] = v.y * scale;
            Qst[(d4 + 2) * 64 + q] = v.z * scale;
            Qst[(d4 + 3) * 64 + q] = v.w * scale;
        }
    }

    float acc[4][4];
    float mrow[4], lrow[4];
#pragma unroll
    for (int i = 0; i < 4; i++) {
        mrow[i] = -INFINITY; lrow[i] = 0.f;
#pragma unroll
        for (int j = 0; j < 4; j++) acc[i][j] = 0.f;
    }

    const unsigned char* mb = mask + (size_t)b * (3 * SEQ);

    for (int kt = 0; kt < SEQ / 64; kt++) {
        __syncthreads();  // previous-iteration P/V reads complete
        // load K^T tile and V tile
        {
            const int d4 = (tid & 15) * 4;
            const int r0 = tid >> 4;
#pragma unroll
            for (int p = 0; p < 4; p++) {
                int kr = r0 + p * 16;
                size_t tok = (size_t)(b * SEQ + kt * 64 + kr) * N3C;
                float4 kv = *(const float4*)(qkv + tok + C_DIM + h * HD + d4);
                KPs[(d4 + 0) * 64 + kr] = kv.x;
                KPs[(d4 + 1) * 64 + kr] = kv.y;
                KPs[(d4 + 2) * 64 + kr] = kv.z;
                KPs[(d4 + 3) * 64 + kr] = kv.w;
                float4 vv = *(const float4*)(qkv + tok + 2 * C_DIM + h * HD + d4);
                *(float4*)(Vs + kr * 64 + d4) = vv;
            }
        }
        __syncthreads();

        // S = Q @ K^T  (4x4 per thread)
        float s[4][4];
#pragma unroll
        for (int i = 0; i < 4; i++)
#pragma unroll
            for (int j = 0; j < 4; j++) s[i][j] = 0.f;
#pragma unroll 8
        for (int dd = 0; dd < HD; dd++) {
            float4 aq = *(const float4*)(Qst + dd * 64 + ty * 4);
            float4 bk = *(const float4*)(KPs + dd * 64 + tx * 4);
            float a_[4] = {aq.x, aq.y, aq.z, aq.w};
            float b_[4] = {bk.x, bk.y, bk.z, bk.w};
#pragma unroll
            for (int i = 0; i < 4; i++)
#pragma unroll
                for (int j = 0; j < 4; j++)
                    s[i][j] = fmaf(a_[i], b_[j], s[i][j]);
        }
        // mask (per key column)
#pragma unroll
        for (int j = 0; j < 4; j++) {
            if (!mb[kt * 64 + tx * 4 + j]) {
#pragma unroll
                for (int i = 0; i < 4; i++) s[i][j] = -INFINITY;
            }
        }
        __syncthreads();  // all K^T reads done before P overwrites KPs

        // online softmax update + write P
#pragma unroll
        for (int i = 0; i < 4; i++) {
            float rmax = fmaxf(fmaxf(s[i][0], s[i][1]), fmaxf(s[i][2], s[i][3]));
#pragma unroll
            for (int off = 8; off; off >>= 1)
                rmax = fmaxf(rmax, __shfl_xor_sync(0xffffffffu, rmax, off));
            float mnew = fmaxf(mrow[i], rmax);
            float factor, psum = 0.f;
            float p0, p1, p2, p3;
            if (mnew == -INFINITY) {           // entire row still fully masked
                factor = 1.f; p0 = p1 = p2 = p3 = 0.f;
            } else {
                factor = __expf(mrow[i] - mnew);   // exp(-inf)=0 on first tile
                p0 = __expf(s[i][0] - mnew);
                p1 = __expf(s[i][1] - mnew);
                p2 = __expf(s[i][2] - mnew);
                p3 = __expf(s[i][3] - mnew);
                psum = p0 + p1 + p2 + p3;
            }
#pragma unroll
            for (int off = 8; off; off >>= 1)
                psum += __shfl_xor_sync(0xffffffffu, psum, off);
            lrow[i] = lrow[i] * factor + psum;
            mrow[i] = mnew;
#pragma unroll
            for (int j = 0; j < 4; j++) acc[i][j] *= factor;
            *(float4*)(KPs + (ty * 4 + i) * 64 + tx * 4) = make_float4(p0, p1, p2, p3);
        }
        __syncthreads();

        // O += P @ V
#pragma unroll 8
        for (int kk = 0; kk < 64; kk++) {
            float a_[4];
#pragma unroll
            for (int i = 0; i < 4; i++) a_[i] = KPs[(ty * 4 + i) * 64 + kk];
            float4 bv = *(const float4*)(Vs + kk * 64 + tx * 4);
            float b_[4] = {bv.x, bv.y, bv.z, bv.w};
#pragma unroll
            for (int i = 0; i < 4; i++)
#pragma unroll
                for (int j = 0; j < 4; j++)
                    acc[i][j] = fmaf(a_[i], b_[j], acc[i][j]);
        }
    }

    // normalize and write xo[b, q, h*64+d]
#pragma unroll
    for (int i = 0; i < 4; i++) {
        int q = qt * 64 + ty * 4 + i;
        float inv = (lrow[i] > 0.f) ? (1.f / lrow[i]) : 0.f;
        float4 o = make_float4(acc[i][0] * inv, acc[i][1] * inv,
                               acc[i][2] * inv, acc[i][3] * inv);
        *(float4*)(xo + (size_t)(b * SEQ + q) * C_DIM + h * HD + tx * 4) = o;
    }
}

// ---------------- launch ---------------------------------------------------
extern "C" void kernel_launch(void* const* d_in, const int* in_sizes, int n_in,
                              void* d_out, int out_size)
{
    const float*         x       = (const float*)d_in[0];
    const unsigned int*  mask_raw= (const unsigned int*)d_in[1];
    const float*         qkv_w   = (const float*)d_in[2];
    const float*         qkv_la  = (const float*)d_in[3];
    const float*         qkv_lb  = (const float*)d_in[4];
    const float*         proj_w  = (const float*)d_in[5];
    const float*         proj_b  = (const float*)d_in[6];
    const float*         proj_la = (const float*)d_in[7];
    const float*         proj_lb = (const float*)d_in[8];
    const float*         fc1_w   = (const float*)d_in[9];
    const float*         fc1_b   = (const float*)d_in[10];
    const float*         fc1_la  = (const float*)d_in[11];
    const float*         fc1_lb  = (const float*)d_in[12];
    const float*         fc2_w   = (const float*)d_in[13];
    const float*         fc2_b   = (const float*)d_in[14];
    const float*         fc2_la  = (const float*)d_in[15];
    const float*         fc2_lb  = (const float*)d_in[16];

    float *qkv_eff, *fc1_eff, *fc2_eff, *proj_eff, *qkvb, *xo, *hb, *yb;
    unsigned char* maskc;
    cudaGetSymbolAddress((void**)&qkv_eff,  g_qkv_eff);
    cudaGetSymbolAddress((void**)&fc1_eff,  g_fc1_eff);
    cudaGetSymbolAddress((void**)&fc2_eff,  g_fc2_eff);
    cudaGetSymbolAddress((void**)&proj_eff, g_proj_eff);
    cudaGetSymbolAddress((void**)&qkvb,     g_qkv);
    cudaGetSymbolAddress((void**)&xo,       g_xo);
    cudaGetSymbolAddress((void**)&hb,       g_h);
    cudaGetSymbolAddress((void**)&yb,       g_y);
    cudaGetSymbolAddress((void**)&maskc,    g_mask);

    // 0) canonicalize mask to uint8
    mask_canon_kernel<<<1, 256>>>(mask_raw, maskc);

    // 1) fold LoRA into weights
    lora_eff_kernel<<<dim3(N3C  / 256, C_DIM), 256>>>(qkv_w,  qkv_la,  qkv_lb,  qkv_eff,  N3C);
    lora_eff_kernel<<<dim3(C_DIM / 256, C_DIM), 256>>>(fc1_w,  fc1_la,  fc1_lb,  fc1_eff,  C_DIM);
    lora_eff_kernel<<<dim3(C_DIM / 256, C_DIM), 256>>>(fc2_w,  fc2_la,  fc2_lb,  fc2_eff,  C_DIM);
    lora_eff_kernel<<<dim3(C_DIM / 256, C_DIM), 256>>>(proj_w, proj_la, proj_lb, proj_eff, C_DIM);

    // 2) qkv = x @ qkv_eff
    sgemm_kernel<<<dim3(N3C / BN, TOKENS / BM), 256>>>(
        x, qkv_eff, nullptr, nullptr, qkvb, TOKENS, N3C, C_DIM, 0);

    // 3) fused masked flash attention -> xo
    attention_kernel<<<dim3(SEQ / 64, HEADS, BATCH), 256>>>(qkvb, maskc, xo);

    // 4) h = gelu(xo @ fc1_eff + fc1_b)
    sgemm_kernel<<<dim3(C_DIM / BN, TOKENS / BM), 256>>>(
        xo, fc1_eff, fc1_b, nullptr, hb, TOKENS, C_DIM, C_DIM, 1);

    // 5) y = xo + (h @ fc2_eff + fc2_b)
    sgemm_kernel<<<dim3(C_DIM / BN, TOKENS / BM), 256>>>(
        hb, fc2_eff, fc2_b, xo, yb, TOKENS, C_DIM, C_DIM, 0);

    // 6) out = y @ proj_eff + proj_b
    sgemm_kernel<<<dim3(C_DIM / BN, TOKENS / BM), 256>>>(
        yb, proj_eff, proj_b, nullptr, (float*)d_out, TOKENS, C_DIM, C_DIM, 0);
}

// round 15
// speedup vs baseline: 1.5817x; 1.5817x over previous
#include <cuda_runtime.h>
#include <cuda_bf16.h>
#include <math.h>
#include <stdint.h>

// Problem constants
#define C_DIM   1024
#define BATCH   8
#define SEQ     512
#define HEADS   16
#define HD      64
#define RANK    32
#define TOKENS  (BATCH*SEQ)     // 4096
#define N3C     (3*C_DIM)       // 3072
#define MASK_N  (BATCH*3*SEQ)   // 12288

// ---------------- scratch (static device memory; no allocs) ----------------
__device__ __align__(256) __nv_bfloat16 g_wqkv_hi[N3C*C_DIM],  g_wqkv_lo[N3C*C_DIM];
__device__ __align__(256) __nv_bfloat16 g_w1_hi [C_DIM*C_DIM], g_w1_lo [C_DIM*C_DIM];
__device__ __align__(256) __nv_bfloat16 g_w2_hi [C_DIM*C_DIM], g_w2_lo [C_DIM*C_DIM];
__device__ __align__(256) __nv_bfloat16 g_wp_hi [C_DIM*C_DIM], g_wp_lo [C_DIM*C_DIM];
__device__ __align__(256) __nv_bfloat16 g_xhi [TOKENS*C_DIM],  g_xlo [TOKENS*C_DIM];
__device__ __align__(256) __nv_bfloat16 g_xohi[TOKENS*C_DIM],  g_xolo[TOKENS*C_DIM];
__device__ __align__(256) __nv_bfloat16 g_hhi [TOKENS*C_DIM],  g_hlo [TOKENS*C_DIM];
__device__ __align__(256) __nv_bfloat16 g_yhi [TOKENS*C_DIM],  g_ylo [TOKENS*C_DIM];
__device__ __align__(256) float g_qkv[TOKENS*N3C];
__device__ __align__(256) float g_xo [TOKENS*C_DIM];
__device__ unsigned char g_mask[MASK_N];

// ---------------- PTX helpers (HMMA / ldmatrix / cp.async) -----------------
__device__ __forceinline__ uint32_t smem_u32(const void* p){
    uint32_t a;
    asm("{ .reg .u64 t; cvta.to.shared.u64 t, %1; cvt.u32.u64 %0, t; }" : "=r"(a) : "l"(p));
    return a;
}
__device__ __forceinline__ void ldsm4(uint32_t* r, uint32_t a){
    asm volatile("ldmatrix.sync.aligned.m8n8.x4.shared.b16 {%0,%1,%2,%3}, [%4];"
        : "=r"(r[0]), "=r"(r[1]), "=r"(r[2]), "=r"(r[3]) : "r"(a));
}
__device__ __forceinline__ void mma_bf16(float* c, const uint32_t* a, const uint32_t* b){
    asm volatile("mma.sync.aligned.m16n8k16.row.col.f32.bf16.bf16.f32 "
        "{%0,%1,%2,%3}, {%4,%5,%6,%7}, {%8,%9}, {%0,%1,%2,%3};"
        : "+f"(c[0]), "+f"(c[1]), "+f"(c[2]), "+f"(c[3])
        : "r"(a[0]), "r"(a[1]), "r"(a[2]), "r"(a[3]), "r"(b[0]), "r"(b[1]));
}
__device__ __forceinline__ void cpasync16(uint32_t s, const void* g){
    asm volatile("cp.async.cg.shared.global [%0], [%1], 16;" :: "r"(s), "l"(g));
}
#define CP_COMMIT() asm volatile("cp.async.commit_group;" ::: "memory")
#define CP_WAIT1()  asm volatile("cp.async.wait_group 1;" ::: "memory")
#define CP_WAIT0()  asm volatile("cp.async.wait_group 0;" ::: "memory")

// ---------------- mask canonicalization (dtype-robust) ---------------------
__global__ void mask_canon_kernel(const unsigned int* __restrict__ m,
                                  unsigned char* __restrict__ out)
{
    __shared__ int flagF, flagBig;
    if (threadIdx.x == 0) { flagF = 0; flagBig = 0; }
    __syncthreads();
    for (int i = threadIdx.x; i < MASK_N / 4; i += blockDim.x) {
        unsigned int w = m[i];
        if (w == 0x3F800000u) atomicOr(&flagF, 1);
        else if (w > 1u)      atomicOr(&flagBig, 1);
    }
    __syncthreads();
    const int mode = flagF ? 2 : (flagBig ? 0 : 1);
    const unsigned char* mu = (const unsigned char*)m;
    const float*         mf = (const float*)m;
    const int*           mi = (const int*)m;
    for (int i = threadIdx.x; i < MASK_N; i += blockDim.x) {
        unsigned char v;
        if (mode == 0)      v = mu[i] ? 1 : 0;
        else if (mode == 1) v = mi[i] ? 1 : 0;
        else                v = (mf[i] != 0.f) ? 1 : 0;
        out[i] = v;
    }
}

// ------------- LoRA fold + transpose + bf16 split: T[n][k] = (W + la@lb)^T -
__global__ __launch_bounds__(256)
void fold_tsplit_kernel(const float* __restrict__ W, const float* __restrict__ la,
                        const float* __restrict__ lb, __nv_bfloat16* __restrict__ Thi,
                        __nv_bfloat16* __restrict__ Tlo, int N)
{
    __shared__ float t[32][33];
    const int tx = threadIdx.x & 31, ty = threadIdx.x >> 5;  // 32x8
    const int n0 = blockIdx.x * 32, k0 = blockIdx.y * 32;
#pragma unroll
    for (int i = 0; i < 4; i++) {
        int k = k0 + ty + 8 * i;
        float acc = W[(size_t)k * N + n0 + tx];
#pragma unroll
        for (int r = 0; r < RANK; r++)
            acc += la[k * RANK + r] * lb[(size_t)r * N + n0 + tx];
        t[ty + 8 * i][tx] = acc;
    }
    __syncthreads();
#pragma unroll
    for (int i = 0; i < 4; i++) {
        int n = n0 + ty + 8 * i;
        float v = t[tx][ty + 8 * i];
        __nv_bfloat16 h = __float2bfloat16(v);
        Thi[(size_t)n * C_DIM + k0 + tx] = h;
        Tlo[(size_t)n * C_DIM + k0 + tx] = __float2bfloat16(v - __bfloat162float(h));
    }
}

// ---------------- elementwise fp32 -> bf16 hi/lo split ---------------------
__global__ __launch_bounds__(256)
void split_kernel(const float* __restrict__ in, __nv_bfloat16* __restrict__ hi,
                  __nv_bfloat16* __restrict__ lo)
{
    int i = blockIdx.x * 256 + threadIdx.x;
    float v = in[i];
    __nv_bfloat16 h = __float2bfloat16(v);
    hi[i] = h;
    lo[i] = __float2bfloat16(v - __bfloat162float(h));
}

__device__ __forceinline__ float gelu_exact(float v)
{
    return 0.5f * v * (1.0f + erff(v * 0.70710678118654752f));
}

// ---------------- HMMA GEMM: C = A @ B^T via 3-term bf16 split -------------
// A: (Ahi,Alo) [M,1024] K-major bf16. B: (Bhi,Blo) [N,1024] K-major bf16.
// 128x128 CTA tile, 8 warps of 64x32 (4x4 m16n8k16 frags), BK=64 chunks,
// cp.async double-buffered smem (row pad to 72 bf16), 3 phases x 16 chunks.
#define LDS_PAD 72
#define TILE_B  (128*LDS_PAD*2)   // 18432 bytes
#define GEMM_SMEM (4*TILE_B)      // 73728 bytes

__global__ __launch_bounds__(256)
void gemm_mma_kernel(const __nv_bfloat16* __restrict__ Ahi, const __nv_bfloat16* __restrict__ Alo,
                     const __nv_bfloat16* __restrict__ Bhi, const __nv_bfloat16* __restrict__ Blo,
                     const float* __restrict__ bias, const float* __restrict__ res,
                     float* __restrict__ C, __nv_bfloat16* __restrict__ Chi,
                     __nv_bfloat16* __restrict__ Clo, int N, int do_gelu)
{
    extern __shared__ __align__(16) char smem[];
    const uint32_t sb = smem_u32(smem);
    const int tid = threadIdx.x, w = tid >> 5, lane = tid & 31;
    const int wm = w >> 2, wn = w & 3;                    // 2x4 warp grid
    const int row0 = blockIdx.y * 128, col0 = blockIdx.x * 128;

    const uint32_t sA[2] = {sb,              sb + TILE_B};
    const uint32_t sB[2] = {sb + 2 * TILE_B, sb + 3 * TILE_B};

    float acc[4][4][4];
#pragma unroll
    for (int i = 0; i < 4; i++)
#pragma unroll
        for (int j = 0; j < 4; j++)
#pragma unroll
            for (int q = 0; q < 4; q++) acc[i][j][q] = 0.f;

    const int lrow = tid >> 3;            // 0..31
    const int lcg  = (tid & 7) * 8;       // 0..56 (bf16 elems)

    auto issue = [&](int c) {
        const int phase = c >> 4, kc = (c & 15) * 64, buf = c & 1;
        const __nv_bfloat16* Ap = (phase < 2)  ? Ahi : Alo;
        const __nv_bfloat16* Bp = (phase == 1) ? Blo : Bhi;
#pragma unroll
        for (int it = 0; it < 4; it++) {
            int r = lrow + 32 * it;
            cpasync16(sA[buf] + (uint32_t)(r * LDS_PAD + lcg) * 2,
                      Ap + (size_t)(row0 + r) * C_DIM + kc + lcg);
            cpasync16(sB[buf] + (uint32_t)(r * LDS_PAD + lcg) * 2,
                      Bp + (size_t)(col0 + r) * C_DIM + kc + lcg);
        }
        CP_COMMIT();
    };

    issue(0);
    for (int c = 0; c < 48; c++) {
        if (c + 1 < 48) { issue(c + 1); CP_WAIT1(); }
        else            { CP_WAIT0(); }
        __syncthreads();
        const int buf = c & 1;
#pragma unroll
        for (int ks = 0; ks < 4; ks++) {
            const int k0 = ks * 16;
            uint32_t af[4][4];
#pragma unroll
            for (int mi = 0; mi < 4; mi++) {
                int r = wm * 64 + mi * 16 + (lane & 15);
                ldsm4(af[mi], sA[buf] + (uint32_t)(r * LDS_PAD + k0 + (lane >> 4) * 8) * 2);
            }
            uint32_t bfg[2][4];
#pragma unroll
            for (int nj = 0; nj < 2; nj++) {
                int n = wn * 32 + nj * 16 + (lane & 7) + ((lane >> 4) & 1) * 8;
                int k = k0 + ((lane >> 3) & 1) * 8;
                ldsm4(bfg[nj], sB[buf] + (uint32_t)(n * LDS_PAD + k) * 2);
            }
#pragma unroll
            for (int mi = 0; mi < 4; mi++)
#pragma unroll
                for (int ti = 0; ti < 4; ti++)
                    mma_bf16(acc[mi][ti], af[mi], &bfg[ti >> 1][(ti & 1) * 2]);
        }
        __syncthreads();
    }

    // ---- epilogue: bias -> gelu -> residual; fp32 and/or bf16 hi/lo out ---
#pragma unroll
    for (int mi = 0; mi < 4; mi++) {
#pragma unroll
        for (int ti = 0; ti < 4; ti++) {
            const int col = col0 + wn * 32 + ti * 8 + (lane & 3) * 2;
#pragma unroll
            for (int half = 0; half < 2; half++) {
                const int row = row0 + wm * 64 + mi * 16 + (lane >> 2) + half * 8;
                float v0 = acc[mi][ti][half * 2 + 0];
                float v1 = acc[mi][ti][half * 2 + 1];
                if (bias) { v0 += bias[col]; v1 += bias[col + 1]; }
                if (do_gelu) { v0 = gelu_exact(v0); v1 = gelu_exact(v1); }
                if (res) {
                    float2 rv = *(const float2*)(res + (size_t)row * N + col);
                    v0 += rv.x; v1 += rv.y;
                }
                if (C) *(float2*)(C + (size_t)row * N + col) = make_float2(v0, v1);
                if (Chi) {
                    __nv_bfloat16 h0 = __float2bfloat16(v0), h1 = __float2bfloat16(v1);
                    __nv_bfloat162 hp; hp.x = h0; hp.y = h1;
                    *(__nv_bfloat162*)(Chi + (size_t)row * N + col) = hp;
                    __nv_bfloat162 lp;
                    lp.x = __float2bfloat16(v0 - __bfloat162float(h0));
                    lp.y = __float2bfloat16(v1 - __bfloat162float(h1));
                    *(__nv_bfloat162*)(Clo + (size_t)row * N + col) = lp;
                }
            }
        }
    }
}

// ---------------- fused masked flash attention (fp32) ----------------------
__global__ __launch_bounds__(256)
void attention_kernel(const float* __restrict__ qkv,
                      const unsigned char* __restrict__ mask,
                      float* __restrict__ xo,
                      __nv_bfloat16* __restrict__ xohi,
                      __nv_bfloat16* __restrict__ xolo)
{
    __shared__ float Qst[HD * 64];
    __shared__ float KPs[64 * 64];
    __shared__ float Vs [64 * 64];

    const int qt = blockIdx.x;
    const int h  = blockIdx.y;
    const int b  = blockIdx.z;
    const int tid = threadIdx.x;
    const int tx = tid & 15;
    const int ty = tid >> 4;
    const float scale = 0.125f;

    {
        const int d4 = (tid & 15) * 4;
        const int r0 = tid >> 4;
#pragma unroll
        for (int p = 0; p < 4; p++) {
            int q = r0 + p * 16;
            float4 v = *(const float4*)(qkv + (size_t)(b * SEQ + qt * 64 + q) * N3C + h * HD + d4);
            Qst[(d4 + 0) * 64 + q] = v.x * scale;
            Qst[(d4 + 1) * 64 + q] = v.y * scale;
            Qst[(d4 + 2) * 64 + q] = v.z * scale;
            Qst[(d4 + 3) * 64 + q] = v.w * scale;
        }
    }

    float acc[4][4];
    float mrow[4], lrow[4];
#pragma unroll
    for (int i = 0; i < 4; i++) {
        mrow[i] = -INFINITY; lrow[i] = 0.f;
#pragma unroll
        for (int j = 0; j < 4; j++) acc[i][j] = 0.f;
    }

    const unsigned char* mb = mask + (size_t)b * (3 * SEQ);

    for (int kt = 0; kt < SEQ / 64; kt++) {
        __syncthreads();
        {
            const int d4 = (tid & 15) * 4;
            const int r0 = tid >> 4;
#pragma unroll
            for (int p = 0; p < 4; p++) {
                int kr = r0 + p * 16;
                size_t tok = (size_t)(b * SEQ + kt * 64 + kr) * N3C;
                float4 kv = *(const float4*)(qkv + tok + C_DIM + h * HD + d4);
                KPs[(d4 + 0) * 64 + kr] = kv.x;
                KPs[(d4 + 1) * 64 + kr] = kv.y;
                KPs[(d4 + 2) * 64 + kr] = kv.z;
                KPs[(d4 + 3) * 64 + kr] = kv.w;
                float4 vv = *(const float4*)(qkv + tok + 2 * C_DIM + h * HD + d4);
                *(float4*)(Vs + kr * 64 + d4) = vv;
            }
        }
        __syncthreads();

        float s[4][4];
#pragma unroll
        for (int i = 0; i < 4; i++)
#pragma unroll
            for (int j = 0; j < 4; j++) s[i][j] = 0.f;
#pragma unroll 8
        for (int dd = 0; dd < HD; dd++) {
            float4 aq = *(const float4*)(Qst + dd * 64 + ty * 4);
            float4 bk = *(const float4*)(KPs + dd * 64 + tx * 4);
            float a_[4] = {aq.x, aq.y, aq.z, aq.w};
            float b_[4] = {bk.x, bk.y, bk.z, bk.w};
#pragma unroll
            for (int i = 0; i < 4; i++)
#pragma unroll
                for (int j = 0; j < 4; j++)
                    s[i][j] = fmaf(a_[i], b_[j], s[i][j]);
        }
#pragma unroll
        for (int j = 0; j < 4; j++) {
            if (!mb[kt * 64 + tx * 4 + j]) {
#pragma unroll
                for (int i = 0; i < 4; i++) s[i][j] = -INFINITY;
            }
        }
        __syncthreads();

#pragma unroll
        for (int i = 0; i < 4; i++) {
            float rmax = fmaxf(fmaxf(s[i][0], s[i][1]), fmaxf(s[i][2], s[i][3]));
#pragma unroll
            for (int off = 8; off; off >>= 1)
                rmax = fmaxf(rmax, __shfl_xor_sync(0xffffffffu, rmax, off));
            float mnew = fmaxf(mrow[i], rmax);
            float factor, psum = 0.f;
            float p0, p1, p2, p3;
            if (mnew == -INFINITY) {
                factor = 1.f; p0 = p1 = p2 = p3 = 0.f;
            } else {
                factor = __expf(mrow[i] - mnew);
                p0 = __expf(s[i][0] - mnew);
                p1 = __expf(s[i][1] - mnew);
                p2 = __expf(s[i][2] - mnew);
                p3 = __expf(s[i][3] - mnew);
                psum = p0 + p1 + p2 + p3;
            }
#pragma unroll
            for (int off = 8; off; off >>= 1)
                psum += __shfl_xor_sync(0xffffffffu, psum, off);
            lrow[i] = lrow[i] * factor + psum;
            mrow[i] = mnew;
#pragma unroll
            for (int j = 0; j < 4; j++) acc[i][j] *= factor;
            *(float4*)(KPs + (ty * 4 + i) * 64 + tx * 4) = make_float4(p0, p1, p2, p3);
        }
        __syncthreads();

#pragma unroll 8
        for (int kk = 0; kk < 64; kk++) {
            float a_[4];
#pragma unroll
            for (int i = 0; i < 4; i++) a_[i] = KPs[(ty * 4 + i) * 64 + kk];
            float4 bv = *(const float4*)(Vs + kk * 64 + tx * 4);
            float b_[4] = {bv.x, bv.y, bv.z, bv.w};
#pragma unroll
            for (int i = 0; i < 4; i++)
#pragma unroll
                for (int j = 0; j < 4; j++)
                    acc[i][j] = fmaf(a_[i], b_[j], acc[i][j]);
        }
    }

#pragma unroll
    for (int i = 0; i < 4; i++) {
        int q = qt * 64 + ty * 4 + i;
        float inv = (lrow[i] > 0.f) ? (1.f / lrow[i]) : 0.f;
        float4 o = make_float4(acc[i][0] * inv, acc[i][1] * inv,
                               acc[i][2] * inv, acc[i][3] * inv);
        size_t off = (size_t)(b * SEQ + q) * C_DIM + h * HD + tx * 4;
        *(float4*)(xo + off) = o;
        __nv_bfloat16 h0 = __float2bfloat16(o.x), h1 = __float2bfloat16(o.y);
        __nv_bfloat16 h2 = __float2bfloat16(o.z), h3 = __float2bfloat16(o.w);
        __nv_bfloat162 hp0; hp0.x = h0; hp0.y = h1;
        __nv_bfloat162 hp1; hp1.x = h2; hp1.y = h3;
        *(__nv_bfloat162*)(xohi + off) = hp0;
        *(__nv_bfloat162*)(xohi + off + 2) = hp1;
        __nv_bfloat162 lp0, lp1;
        lp0.x = __float2bfloat16(o.x - __bfloat162float(h0));
        lp0.y = __float2bfloat16(o.y - __bfloat162float(h1));
        lp1.x = __float2bfloat16(o.z - __bfloat162float(h2));
        lp1.y = __float2bfloat16(o.w - __bfloat162float(h3));
        *(__nv_bfloat162*)(xolo + off) = lp0;
        *(__nv_bfloat162*)(xolo + off + 2) = lp1;
    }
}

// ---------------- launch ---------------------------------------------------
extern "C" void kernel_launch(void* const* d_in, const int* in_sizes, int n_in,
                              void* d_out, int out_size)
{
    const float*         x       = (const float*)d_in[0];
    const unsigned int*  mask_raw= (const unsigned int*)d_in[1];
    const float*         qkv_w   = (const float*)d_in[2];
    const float*         qkv_la  = (const float*)d_in[3];
    const float*         qkv_lb  = (const float*)d_in[4];
    const float*         proj_w  = (const float*)d_in[5];
    const float*         proj_b  = (const float*)d_in[6];
    const float*         proj_la = (const float*)d_in[7];
    const float*         proj_lb = (const float*)d_in[8];
    const float*         fc1_w   = (const float*)d_in[9];
    const float*         fc1_b   = (const float*)d_in[10];
    const float*         fc1_la  = (const float*)d_in[11];
    const float*         fc1_lb  = (const float*)d_in[12];
    const float*         fc2_w   = (const float*)d_in[13];
    const float*         fc2_b   = (const float*)d_in[14];
    const float*         fc2_la  = (const float*)d_in[15];
    const float*         fc2_lb  = (const float*)d_in[16];

    __nv_bfloat16 *wqkv_hi, *wqkv_lo, *w1_hi, *w1_lo, *w2_hi, *w2_lo, *wp_hi, *wp_lo;
    __nv_bfloat16 *xhi, *xlo, *xohi, *xolo, *hhi, *hlo, *yhi, *ylo;
    float *qkvb, *xo;
    unsigned char* maskc;
    cudaGetSymbolAddress((void**)&wqkv_hi, g_wqkv_hi);
    cudaGetSymbolAddress((void**)&wqkv_lo, g_wqkv_lo);
    cudaGetSymbolAddress((void**)&w1_hi,   g_w1_hi);
    cudaGetSymbolAddress((void**)&w1_lo,   g_w1_lo);
    cudaGetSymbolAddress((void**)&w2_hi,   g_w2_hi);
    cudaGetSymbolAddress((void**)&w2_lo,   g_w2_lo);
    cudaGetSymbolAddress((void**)&wp_hi,   g_wp_hi);
    cudaGetSymbolAddress((void**)&wp_lo,   g_wp_lo);
    cudaGetSymbolAddress((void**)&xhi,     g_xhi);
    cudaGetSymbolAddress((void**)&xlo,     g_xlo);
    cudaGetSymbolAddress((void**)&xohi,    g_xohi);
    cudaGetSymbolAddress((void**)&xolo,    g_xolo);
    cudaGetSymbolAddress((void**)&hhi,     g_hhi);
    cudaGetSymbolAddress((void**)&hlo,     g_hlo);
    cudaGetSymbolAddress((void**)&yhi,     g_yhi);
    cudaGetSymbolAddress((void**)&ylo,     g_ylo);
    cudaGetSymbolAddress((void**)&qkvb,    g_qkv);
    cudaGetSymbolAddress((void**)&xo,      g_xo);
    cudaGetSymbolAddress((void**)&maskc,   g_mask);

    cudaFuncSetAttribute(gemm_mma_kernel,
                         cudaFuncAttributeMaxDynamicSharedMemorySize, GEMM_SMEM);

    // 0) canonicalize mask
    mask_canon_kernel<<<1, 256>>>(mask_raw, maskc);

    // 1) fold LoRA + transpose + bf16 split for all 4 weights
    fold_tsplit_kernel<<<dim3(N3C / 32, C_DIM / 32), 256>>>(qkv_w,  qkv_la,  qkv_lb,  wqkv_hi, wqkv_lo, N3C);
    fold_tsplit_kernel<<<dim3(C_DIM / 32, C_DIM / 32), 256>>>(fc1_w,  fc1_la,  fc1_lb,  w1_hi,  w1_lo,  C_DIM);
    fold_tsplit_kernel<<<dim3(C_DIM / 32, C_DIM / 32), 256>>>(fc2_w,  fc2_la,  fc2_lb,  w2_hi,  w2_lo,  C_DIM);
    fold_tsplit_kernel<<<dim3(C_DIM / 32, C_DIM / 32), 256>>>(proj_w, proj_la, proj_lb, wp_hi,  wp_lo,  C_DIM);

    // 2) split x
    split_kernel<<<TOKENS * C_DIM / 256, 256>>>(x, xhi, xlo);

    // 3) qkv = x @ Wqkv  (fp32 out)
    gemm_mma_kernel<<<dim3(N3C / 128, TOKENS / 128), 256, GEMM_SMEM>>>(
        xhi, xlo, wqkv_hi, wqkv_lo, nullptr, nullptr, qkvb, nullptr, nullptr, N3C, 0);

    // 4) attention -> xo (fp32 + bf16 splits)
    attention_kernel<<<dim3(SEQ / 64, HEADS, BATCH), 256>>>(qkvb, maskc, xo, xohi, xolo);

    // 5) h = gelu(xo @ W1 + b1) -> bf16 splits only
    gemm_mma_kernel<<<dim3(C_DIM / 128, TOKENS / 128), 256, GEMM_SMEM>>>(
        xohi, xolo, w1_hi, w1_lo, fc1_b, nullptr, nullptr, hhi, hlo, C_DIM, 1);

    // 6) y = xo + (h @ W2 + b2) -> bf16 splits only
    gemm_mma_kernel<<<dim3(C_DIM / 128, TOKENS / 128), 256, GEMM_SMEM>>>(
        hhi, hlo, w2_hi, w2_lo, fc2_b, xo, nullptr, yhi, ylo, C_DIM, 0);

    // 7) out = y @ Wp + bp  (fp32 out)
    gemm_mma_kernel<<<dim3(C_DIM / 128, TOKENS / 128), 256, GEMM_SMEM>>>(
        yhi, ylo, wp_hi, wp_lo, proj_b, nullptr, (float*)d_out, nullptr, nullptr, C_DIM, 0);
}

// round 17
// speedup vs baseline: 1.8504x; 1.1699x over previous
#include <cuda_runtime.h>
#include <cuda_bf16.h>
#include <math.h>
#include <stdint.h>

// Problem constants
#define C_DIM   1024
#define BATCH   8
#define SEQ     512
#define HEADS   16
#define HD      64
#define RANK    32
#define TOKENS  (BATCH*SEQ)     // 4096
#define N3C     (3*C_DIM)       // 3072
#define MASK_N  (BATCH*3*SEQ)   // 12288

// ---------------- scratch (static device memory; no allocs) ----------------
__device__ __align__(256) __nv_bfloat16 g_wqkv_hi[N3C*C_DIM],  g_wqkv_lo[N3C*C_DIM];
__device__ __align__(256) __nv_bfloat16 g_w1_hi [C_DIM*C_DIM], g_w1_lo [C_DIM*C_DIM];
__device__ __align__(256) __nv_bfloat16 g_w2_hi [C_DIM*C_DIM], g_w2_lo [C_DIM*C_DIM];
__device__ __align__(256) __nv_bfloat16 g_wp_hi [C_DIM*C_DIM], g_wp_lo [C_DIM*C_DIM];
__device__ __align__(256) __nv_bfloat16 g_xhi [TOKENS*C_DIM],  g_xlo [TOKENS*C_DIM];
__device__ __align__(256) __nv_bfloat16 g_qkvhi[TOKENS*N3C],   g_qkvlo[TOKENS*N3C];
__device__ __align__(256) __nv_bfloat16 g_xohi[TOKENS*C_DIM],  g_xolo[TOKENS*C_DIM];
__device__ __align__(256) __nv_bfloat16 g_hhi [TOKENS*C_DIM],  g_hlo [TOKENS*C_DIM];
__device__ __align__(256) __nv_bfloat16 g_yhi [TOKENS*C_DIM],  g_ylo [TOKENS*C_DIM];
__device__ __align__(256) float g_xo [TOKENS*C_DIM];
__device__ unsigned char g_mask[MASK_N];

// ---------------- PTX helpers (HMMA / ldmatrix / cp.async) -----------------
__device__ __forceinline__ uint32_t smem_u32(const void* p){
    uint32_t a;
    asm("{ .reg .u64 t; cvta.to.shared.u64 t, %1; cvt.u32.u64 %0, t; }" : "=r"(a) : "l"(p));
    return a;
}
__device__ __forceinline__ void ldsm4(uint32_t* r, uint32_t a){
    asm volatile("ldmatrix.sync.aligned.m8n8.x4.shared.b16 {%0,%1,%2,%3}, [%4];"
        : "=r"(r[0]), "=r"(r[1]), "=r"(r[2]), "=r"(r[3]) : "r"(a));
}
__device__ __forceinline__ void mma_bf16(float* c, const uint32_t* a, const uint32_t* b){
    asm volatile("mma.sync.aligned.m16n8k16.row.col.f32.bf16.bf16.f32 "
        "{%0,%1,%2,%3}, {%4,%5,%6,%7}, {%8,%9}, {%0,%1,%2,%3};"
        : "+f"(c[0]), "+f"(c[1]), "+f"(c[2]), "+f"(c[3])
        : "r"(a[0]), "r"(a[1]), "r"(a[2]), "r"(a[3]), "r"(b[0]), "r"(b[1]));
}
__device__ __forceinline__ void cpasync16(uint32_t s, const void* g){
    asm volatile("cp.async.cg.shared.global [%0], [%1], 16;" :: "r"(s), "l"(g));
}
#define CP_COMMIT() asm volatile("cp.async.commit_group;" ::: "memory")
#define CP_WAIT1()  asm volatile("cp.async.wait_group 1;" ::: "memory")
#define CP_WAIT0()  asm volatile("cp.async.wait_group 0;" ::: "memory")

__device__ __forceinline__ uint32_t pack_bf2(float a, float b){
    __nv_bfloat162 t; t.x = __float2bfloat16(a); t.y = __float2bfloat16(b);
    return *(uint32_t*)&t;
}

// ---------------- mask canonicalization (dtype-robust) ---------------------
__global__ void mask_canon_kernel(const unsigned int* __restrict__ m,
                                  unsigned char* __restrict__ out)
{
    __shared__ int flagF, flagBig;
    if (threadIdx.x == 0) { flagF = 0; flagBig = 0; }
    __syncthreads();
    for (int i = threadIdx.x; i < MASK_N / 4; i += blockDim.x) {
        unsigned int w = m[i];
        if (w == 0x3F800000u) atomicOr(&flagF, 1);
        else if (w > 1u)      atomicOr(&flagBig, 1);
    }
    __syncthreads();
    const int mode = flagF ? 2 : (flagBig ? 0 : 1);
    const unsigned char* mu = (const unsigned char*)m;
    const float*         mf = (const float*)m;
    const int*           mi = (const int*)m;
    for (int i = threadIdx.x; i < MASK_N; i += blockDim.x) {
        unsigned char v;
        if (mode == 0)      v = mu[i] ? 1 : 0;
        else if (mode == 1) v = mi[i] ? 1 : 0;
        else                v = (mf[i] != 0.f) ? 1 : 0;
        out[i] = v;
    }
}

// ------------- LoRA fold + transpose + bf16 split: T[n][k] = (W + la@lb)^T -
__global__ __launch_bounds__(256)
void fold_tsplit_kernel(const float* __restrict__ W, const float* __restrict__ la,
                        const float* __restrict__ lb, __nv_bfloat16* __restrict__ Thi,
                        __nv_bfloat16* __restrict__ Tlo, int N)
{
    __shared__ float t[32][33];
    const int tx = threadIdx.x & 31, ty = threadIdx.x >> 5;  // 32x8
    const int n0 = blockIdx.x * 32, k0 = blockIdx.y * 32;
#pragma unroll
    for (int i = 0; i < 4; i++) {
        int k = k0 + ty + 8 * i;
        float acc = W[(size_t)k * N + n0 + tx];
#pragma unroll
        for (int r = 0; r < RANK; r++)
            acc += la[k * RANK + r] * lb[(size_t)r * N + n0 + tx];
        t[ty + 8 * i][tx] = acc;
    }
    __syncthreads();
#pragma unroll
    for (int i = 0; i < 4; i++) {
        int n = n0 + ty + 8 * i;
        float v = t[tx][ty + 8 * i];
        __nv_bfloat16 h = __float2bfloat16(v);
        Thi[(size_t)n * C_DIM + k0 + tx] = h;
        Tlo[(size_t)n * C_DIM + k0 + tx] = __float2bfloat16(v - __bfloat162float(h));
    }
}

// ---------------- elementwise fp32 -> bf16 hi/lo split ---------------------
__global__ __launch_bounds__(256)
void split_kernel(const float* __restrict__ in, __nv_bfloat16* __restrict__ hi,
                  __nv_bfloat16* __restrict__ lo)
{
    int i = blockIdx.x * 256 + threadIdx.x;
    float v = in[i];
    __nv_bfloat16 h = __float2bfloat16(v);
    hi[i] = h;
    lo[i] = __float2bfloat16(v - __bfloat162float(h));
}

__device__ __forceinline__ float gelu_exact(float v)
{
    return 0.5f * v * (1.0f + erff(v * 0.70710678118654752f));
}

// ---------------- HMMA GEMM: C = A @ B^T via 3-term bf16 split -------------
#define LDS_PAD 72
#define TILE_B  (128*LDS_PAD*2)   // 18432 bytes
#define GEMM_SMEM (4*TILE_B)      // 73728 bytes

__global__ __launch_bounds__(256)
void gemm_mma_kernel(const __nv_bfloat16* __restrict__ Ahi, const __nv_bfloat16* __restrict__ Alo,
                     const __nv_bfloat16* __restrict__ Bhi, const __nv_bfloat16* __restrict__ Blo,
                     const float* __restrict__ bias, const float* __restrict__ res,
                     float* __restrict__ C, __nv_bfloat16* __restrict__ Chi,
                     __nv_bfloat16* __restrict__ Clo, int N, int do_gelu)
{
    extern __shared__ __align__(16) char smem[];
    const uint32_t sb = smem_u32(smem);
    const int tid = threadIdx.x, w = tid >> 5, lane = tid & 31;
    const int wm = w >> 2, wn = w & 3;                    // 2x4 warp grid
    const int row0 = blockIdx.y * 128, col0 = blockIdx.x * 128;

    const uint32_t sA[2] = {sb,              sb + TILE_B};
    const uint32_t sB[2] = {sb + 2 * TILE_B, sb + 3 * TILE_B};

    float acc[4][4][4];
#pragma unroll
    for (int i = 0; i < 4; i++)
#pragma unroll
        for (int j = 0; j < 4; j++)
#pragma unroll
            for (int q = 0; q < 4; q++) acc[i][j][q] = 0.f;

    const int lrow = tid >> 3;            // 0..31
    const int lcg  = (tid & 7) * 8;       // 0..56 (bf16 elems)

    auto issue = [&](int c) {
        const int phase = c >> 4, kc = (c & 15) * 64, buf = c & 1;
        const __nv_bfloat16* Ap = (phase < 2)  ? Ahi : Alo;
        const __nv_bfloat16* Bp = (phase == 1) ? Blo : Bhi;
#pragma unroll
        for (int it = 0; it < 4; it++) {
            int r = lrow + 32 * it;
            cpasync16(sA[buf] + (uint32_t)(r * LDS_PAD + lcg) * 2,
                      Ap + (size_t)(row0 + r) * C_DIM + kc + lcg);
            cpasync16(sB[buf] + (uint32_t)(r * LDS_PAD + lcg) * 2,
                      Bp + (size_t)(col0 + r) * C_DIM + kc + lcg);
        }
        CP_COMMIT();
    };

    issue(0);
    for (int c = 0; c < 48; c++) {
        if (c + 1 < 48) { issue(c + 1); CP_WAIT1(); }
        else            { CP_WAIT0(); }
        __syncthreads();
        const int buf = c & 1;
#pragma unroll
        for (int ks = 0; ks < 4; ks++) {
            const int k0 = ks * 16;
            uint32_t af[4][4];
#pragma unroll
            for (int mi = 0; mi < 4; mi++) {
                int r = wm * 64 + mi * 16 + (lane & 15);
                ldsm4(af[mi], sA[buf] + (uint32_t)(r * LDS_PAD + k0 + (lane >> 4) * 8) * 2);
            }
            uint32_t bfg[2][4];
#pragma unroll
            for (int nj = 0; nj < 2; nj++) {
                int n = wn * 32 + nj * 16 + (lane & 7) + ((lane >> 4) & 1) * 8;
                int k = k0 + ((lane >> 3) & 1) * 8;
                ldsm4(bfg[nj], sB[buf] + (uint32_t)(n * LDS_PAD + k) * 2);
            }
#pragma unroll
            for (int mi = 0; mi < 4; mi++)
#pragma unroll
                for (int ti = 0; ti < 4; ti++)
                    mma_bf16(acc[mi][ti], af[mi], &bfg[ti >> 1][(ti & 1) * 2]);
        }
        __syncthreads();
    }

#pragma unroll
    for (int mi = 0; mi < 4; mi++) {
#pragma unroll
        for (int ti = 0; ti < 4; ti++) {
            const int col = col0 + wn * 32 + ti * 8 + (lane & 3) * 2;
#pragma unroll
            for (int half = 0; half < 2; half++) {
                const int row = row0 + wm * 64 + mi * 16 + (lane >> 2) + half * 8;
                float v0 = acc[mi][ti][half * 2 + 0];
                float v1 = acc[mi][ti][half * 2 + 1];
                if (bias) { v0 += bias[col]; v1 += bias[col + 1]; }
                if (do_gelu) { v0 = gelu_exact(v0); v1 = gelu_exact(v1); }
                if (res) {
                    float2 rv = *(const float2*)(res + (size_t)row * N + col);
                    v0 += rv.x; v1 += rv.y;
                }
                if (C) *(float2*)(C + (size_t)row * N + col) = make_float2(v0, v1);
                if (Chi) {
                    __nv_bfloat16 h0 = __float2bfloat16(v0), h1 = __float2bfloat16(v1);
                    __nv_bfloat162 hp; hp.x = h0; hp.y = h1;
                    *(__nv_bfloat162*)(Chi + (size_t)row * N + col) = hp;
                    __nv_bfloat162 lp;
                    lp.x = __float2bfloat16(v0 - __bfloat162float(h0));
                    lp.y = __float2bfloat16(v1 - __bfloat162float(h1));
                    *(__nv_bfloat162*)(Clo + (size_t)row * N + col) = lp;
                }
            }
        }
    }
}

// ---------------- HMMA flash attention (3-term bf16 split) -----------------
// qkv hi/lo: [4096, 3072] bf16. CTA = (qt, h, b), 128 threads (4 warps),
// warp w owns q rows w*16..w*16+15. Online softmax in C-fragment registers.
#define APAD 72
#define AQ_B (64*APAD*2)          // 9216 bytes per tile buffer
#define ATT_SMEM (6*AQ_B)         // 55296

__global__ __launch_bounds__(128)
void attention_mma_kernel(const __nv_bfloat16* __restrict__ qvh,
                          const __nv_bfloat16* __restrict__ qvl,
                          const unsigned char* __restrict__ mask,
                          float* __restrict__ xo,
                          __nv_bfloat16* __restrict__ xohi,
                          __nv_bfloat16* __restrict__ xolo)
{
    extern __shared__ __align__(16) char asmem[];
    const uint32_t sb = smem_u32(asmem);
    const uint32_t QHI = sb,            QLO = sb + AQ_B;
    const uint32_t KHI = sb + 2*AQ_B,   KLO = sb + 3*AQ_B;
    const uint32_t VHI = sb + 4*AQ_B,   VLO = sb + 5*AQ_B;
    __nv_bfloat16* pQhi = (__nv_bfloat16*)(asmem);
    __nv_bfloat16* pQlo = (__nv_bfloat16*)(asmem + AQ_B);
    __nv_bfloat16* pKhi = (__nv_bfloat16*)(asmem + 2*AQ_B);
    __nv_bfloat16* pKlo = (__nv_bfloat16*)(asmem + 3*AQ_B);
    __nv_bfloat16* pVhi = (__nv_bfloat16*)(asmem + 4*AQ_B);
    __nv_bfloat16* pVlo = (__nv_bfloat16*)(asmem + 5*AQ_B);

    const int qt = blockIdx.x, h = blockIdx.y, b = blockIdx.z;
    const int tid = threadIdx.x, w = tid >> 5, lane = tid & 31;
    const int g = lane >> 2, t4 = lane & 3;
    const unsigned char* mb = mask + (size_t)b * (3 * SEQ);

    // ---- load Q tile (64 x 64), hi/lo, K-major [q][d] ----
    {
        const int r = tid >> 1, d0 = (tid & 1) * 32;
        size_t base = (size_t)(b * SEQ + qt * 64 + r) * N3C + h * HD + d0;
#pragma unroll
        for (int i = 0; i < 4; i++) {
            *(uint4*)(pQhi + r * APAD + d0 + i * 8) = *(const uint4*)(qvh + base + i * 8);
            *(uint4*)(pQlo + r * APAD + d0 + i * 8) = *(const uint4*)(qvl + base + i * 8);
        }
    }

    float oo[8][4];
#pragma unroll
    for (int i = 0; i < 8; i++)
#pragma unroll
        for (int j = 0; j < 4; j++) oo[i][j] = 0.f;
    float m0 = -INFINITY, m1 = -INFINITY, l0 = 0.f, l1 = 0.f;

    for (int kt = 0; kt < SEQ / 64; kt++) {
        __syncthreads();   // prior-tile smem reads complete
        // ---- load K tile [key][d] and V tile transposed [d][key] ----
        {
            const int r = tid >> 1, d0 = (tid & 1) * 32;
            size_t kb = (size_t)(b * SEQ + kt * 64 + r) * N3C + C_DIM + h * HD + d0;
#pragma unroll
            for (int i = 0; i < 4; i++) {
                *(uint4*)(pKhi + r * APAD + d0 + i * 8) = *(const uint4*)(qvh + kb + i * 8);
                *(uint4*)(pKlo + r * APAD + d0 + i * 8) = *(const uint4*)(qvl + kb + i * 8);
            }
            size_t vb = kb + C_DIM;
#pragma unroll
            for (int i = 0; i < 4; i++) {
                union { uint4 u; __nv_bfloat16 e[8]; } ch, cl;
                ch.u = *(const uint4*)(qvh + vb + i * 8);
                cl.u = *(const uint4*)(qvl + vb + i * 8);
#pragma unroll
                for (int j = 0; j < 8; j++) {
                    pVhi[(d0 + i * 8 + j) * APAD + r] = ch.e[j];
                    pVlo[(d0 + i * 8 + j) * APAD + r] = cl.e[j];
                }
            }
        }
        __syncthreads();

        // ---- S = Q @ K^T : 3 phases ----
        float s[8][4];
#pragma unroll
        for (int i = 0; i < 8; i++)
#pragma unroll
            for (int j = 0; j < 4; j++) s[i][j] = 0.f;
#pragma unroll
        for (int ph = 0; ph < 3; ph++) {
            const uint32_t Qb = (ph < 2)  ? QHI : QLO;
            const uint32_t Kb = (ph == 1) ? KLO : KHI;
#pragma unroll
            for (int ks = 0; ks < 4; ks++) {
                uint32_t af[4];
                ldsm4(af, Qb + (uint32_t)((w * 16 + (lane & 15)) * APAD + ks * 16 + (lane >> 4) * 8) * 2);
                uint32_t bfg[4][4];
#pragma unroll
                for (int nj = 0; nj < 4; nj++) {
                    int n = nj * 16 + (lane & 7) + ((lane >> 4) & 1) * 8;
                    int k = ks * 16 + ((lane >> 3) & 1) * 8;
                    ldsm4(bfg[nj], Kb + (uint32_t)(n * APAD + k) * 2);
                }
#pragma unroll
                for (int ti = 0; ti < 8; ti++)
                    mma_bf16(s[ti], af, &bfg[ti >> 1][(ti & 1) * 2]);
            }
        }

        // ---- scale + mask + online softmax (in fragment registers) ----
        float rmax0 = -INFINITY, rmax1 = -INFINITY;
#pragma unroll
        for (int ti = 0; ti < 8; ti++) {
            int c0 = kt * 64 + ti * 8 + t4 * 2;
            bool m0ok = mb[c0] != 0, m1ok = mb[c0 + 1] != 0;
            s[ti][0] = m0ok ? s[ti][0] * 0.125f : -INFINITY;
            s[ti][1] = m1ok ? s[ti][1] * 0.125f : -INFINITY;
            s[ti][2] = m0ok ? s[ti][2] * 0.125f : -INFINITY;
            s[ti][3] = m1ok ? s[ti][3] * 0.125f : -INFINITY;
            rmax0 = fmaxf(rmax0, fmaxf(s[ti][0], s[ti][1]));
            rmax1 = fmaxf(rmax1, fmaxf(s[ti][2], s[ti][3]));
        }
        rmax0 = fmaxf(rmax0, __shfl_xor_sync(0xffffffffu, rmax0, 1));
        rmax0 = fmaxf(rmax0, __shfl_xor_sync(0xffffffffu, rmax0, 2));
        rmax1 = fmaxf(rmax1, __shfl_xor_sync(0xffffffffu, rmax1, 1));
        rmax1 = fmaxf(rmax1, __shfl_xor_sync(0xffffffffu, rmax1, 2));
        float mnew0 = fmaxf(m0, rmax0), mnew1 = fmaxf(m1, rmax1);
        float f0 = (mnew0 == -INFINITY) ? 1.f : __expf(m0 - mnew0);
        float f1 = (mnew1 == -INFINITY) ? 1.f : __expf(m1 - mnew1);
        float ps0 = 0.f, ps1 = 0.f;
#pragma unroll
        for (int ti = 0; ti < 8; ti++) {
            float p0 = (mnew0 == -INFINITY) ? 0.f : __expf(s[ti][0] - mnew0);
            float p1 = (mnew0 == -INFINITY) ? 0.f : __expf(s[ti][1] - mnew0);
            float p2 = (mnew1 == -INFINITY) ? 0.f : __expf(s[ti][2] - mnew1);
            float p3 = (mnew1 == -INFINITY) ? 0.f : __expf(s[ti][3] - mnew1);
            s[ti][0] = p0; s[ti][1] = p1; s[ti][2] = p2; s[ti][3] = p3;
            ps0 += p0 + p1; ps1 += p2 + p3;
        }
        ps0 += __shfl_xor_sync(0xffffffffu, ps0, 1);
        ps0 += __shfl_xor_sync(0xffffffffu, ps0, 2);
        ps1 += __shfl_xor_sync(0xffffffffu, ps1, 1);
        ps1 += __shfl_xor_sync(0xffffffffu, ps1, 2);
        l0 = l0 * f0 + ps0; l1 = l1 * f1 + ps1;
        m0 = mnew0; m1 = mnew1;
#pragma unroll
        for (int ti = 0; ti < 8; ti++) {
            oo[ti][0] *= f0; oo[ti][1] *= f0;
            oo[ti][2] *= f1; oo[ti][3] *= f1;
        }

        // ---- O += P @ V : 3 phases (Phi*Vhi, Phi*Vlo, Plo*Vhi) ----
#pragma unroll
        for (int ks = 0; ks < 4; ks++) {
            uint32_t bh[4][4], bl[4][4];
#pragma unroll
            for (int nj = 0; nj < 4; nj++) {
                int n = nj * 16 + (lane & 7) + ((lane >> 4) & 1) * 8;
                int k = ks * 16 + ((lane >> 3) & 1) * 8;
                ldsm4(bh[nj], VHI + (uint32_t)(n * APAD + k) * 2);
                ldsm4(bl[nj], VLO + (uint32_t)(n * APAD + k) * 2);
            }
            // A frags from P tiles 2ks (k 0-7) and 2ks+1 (k 8-15)
            float* t0 = s[2 * ks];
            float* t1 = s[2 * ks + 1];
            uint32_t ahi[4], alo[4];
            {
                float h00 = __bfloat162float(__float2bfloat16(t0[0]));
                float h01 = __bfloat162float(__float2bfloat16(t0[1]));
                float h02 = __bfloat162float(__float2bfloat16(t0[2]));
                float h03 = __bfloat162float(__float2bfloat16(t0[3]));
                float h10 = __bfloat162float(__float2bfloat16(t1[0]));
                float h11 = __bfloat162float(__float2bfloat16(t1[1]));
                float h12 = __bfloat162float(__float2bfloat16(t1[2]));
                float h13 = __bfloat162float(__float2bfloat16(t1[3]));
                ahi[0] = pack_bf2(h00, h01); ahi[1] = pack_bf2(h02, h03);
                ahi[2] = pack_bf2(h10, h11); ahi[3] = pack_bf2(h12, h13);
                alo[0] = pack_bf2(t0[0] - h00, t0[1] - h01);
                alo[1] = pack_bf2(t0[2] - h02, t0[3] - h03);
                alo[2] = pack_bf2(t1[0] - h10, t1[1] - h11);
                alo[3] = pack_bf2(t1[2] - h12, t1[3] - h13);
            }
#pragma unroll
            for (int ti = 0; ti < 8; ti++) {
                mma_bf16(oo[ti], ahi, &bh[ti >> 1][(ti & 1) * 2]);
                mma_bf16(oo[ti], ahi, &bl[ti >> 1][(ti & 1) * 2]);
                mma_bf16(oo[ti], alo, &bh[ti >> 1][(ti & 1) * 2]);
            }
        }
    }

    // ---- normalize + write xo (fp32 + bf16 hi/lo) ----
    const float inv0 = (l0 > 0.f) ? (1.f / l0) : 0.f;
    const float inv1 = (l1 > 0.f) ? (1.f / l1) : 0.f;
#pragma unroll
    for (int ti = 0; ti < 8; ti++) {
        const int dcol = ti * 8 + t4 * 2;
#pragma unroll
        for (int half = 0; half < 2; half++) {
            const int row = qt * 64 + w * 16 + g + half * 8;
            const float inv = half ? inv1 : inv0;
            float v0 = oo[ti][half * 2 + 0] * inv;
            float v1 = oo[ti][half * 2 + 1] * inv;
            size_t off = (size_t)(b * SEQ + row) * C_DIM + h * HD + dcol;
            *(float2*)(xo + off) = make_float2(v0, v1);
            __nv_bfloat16 h0 = __float2bfloat16(v0), h1 = __float2bfloat16(v1);
            __nv_bfloat162 hp; hp.x = h0; hp.y = h1;
            *(__nv_bfloat162*)(xohi + off) = hp;
            __nv_bfloat162 lp;
            lp.x = __float2bfloat16(v0 - __bfloat162float(h0));
            lp.y = __float2bfloat16(v1 - __bfloat162float(h1));
            *(__nv_bfloat162*)(xolo + off) = lp;
        }
    }
}

// ---------------- launch ---------------------------------------------------
extern "C" void kernel_launch(void* const* d_in, const int* in_sizes, int n_in,
                              void* d_out, int out_size)
{
    const float*         x       = (const float*)d_in[0];
    const unsigned int*  mask_raw= (const unsigned int*)d_in[1];
    const float*         qkv_w   = (const float*)d_in[2];
    const float*         qkv_la  = (const float*)d_in[3];
    const float*         qkv_lb  = (const float*)d_in[4];
    const float*         proj_w  = (const float*)d_in[5];
    const float*         proj_b  = (const float*)d_in[6];
    const float*         proj_la = (const float*)d_in[7];
    const float*         proj_lb = (const float*)d_in[8];
    const float*         fc1_w   = (const float*)d_in[9];
    const float*         fc1_b   = (const float*)d_in[10];
    const float*         fc1_la  = (const float*)d_in[11];
    const float*         fc1_lb  = (const float*)d_in[12];
    const float*         fc2_w   = (const float*)d_in[13];
    const float*         fc2_b   = (const float*)d_in[14];
    const float*         fc2_la  = (const float*)d_in[15];
    const float*         fc2_lb  = (const float*)d_in[16];

    __nv_bfloat16 *wqkv_hi, *wqkv_lo, *w1_hi, *w1_lo, *w2_hi, *w2_lo, *wp_hi, *wp_lo;
    __nv_bfloat16 *xhi, *xlo, *qkvhi, *qkvlo, *xohi, *xolo, *hhi, *hlo, *yhi, *ylo;
    float *xo;
    unsigned char* maskc;
    cudaGetSymbolAddress((void**)&wqkv_hi, g_wqkv_hi);
    cudaGetSymbolAddress((void**)&wqkv_lo, g_wqkv_lo);
    cudaGetSymbolAddress((void**)&w1_hi,   g_w1_hi);
    cudaGetSymbolAddress((void**)&w1_lo,   g_w1_lo);
    cudaGetSymbolAddress((void**)&w2_hi,   g_w2_hi);
    cudaGetSymbolAddress((void**)&w2_lo,   g_w2_lo);
    cudaGetSymbolAddress((void**)&wp_hi,   g_wp_hi);
    cudaGetSymbolAddress((void**)&wp_lo,   g_wp_lo);
    cudaGetSymbolAddress((void**)&xhi,     g_xhi);
    cudaGetSymbolAddress((void**)&xlo,     g_xlo);
    cudaGetSymbolAddress((void**)&qkvhi,   g_qkvhi);
    cudaGetSymbolAddress((void**)&qkvlo,   g_qkvlo);
    cudaGetSymbolAddress((void**)&xohi,    g_xohi);
    cudaGetSymbolAddress((void**)&xolo,    g_xolo);
    cudaGetSymbolAddress((void**)&hhi,     g_hhi);
    cudaGetSymbolAddress((void**)&hlo,     g_hlo);
    cudaGetSymbolAddress((void**)&yhi,     g_yhi);
    cudaGetSymbolAddress((void**)&ylo,     g_ylo);
    cudaGetSymbolAddress((void**)&xo,      g_xo);
    cudaGetSymbolAddress((void**)&maskc,   g_mask);

    cudaFuncSetAttribute(gemm_mma_kernel,
                         cudaFuncAttributeMaxDynamicSharedMemorySize, GEMM_SMEM);
    cudaFuncSetAttribute(attention_mma_kernel,
                         cudaFuncAttributeMaxDynamicSharedMemorySize, ATT_SMEM);

    // 0) canonicalize mask
    mask_canon_kernel<<<1, 256>>>(mask_raw, maskc);

    // 1) fold LoRA + transpose + bf16 split for all 4 weights
    fold_tsplit_kernel<<<dim3(N3C / 32, C_DIM / 32), 256>>>(qkv_w,  qkv_la,  qkv_lb,  wqkv_hi, wqkv_lo, N3C);
    fold_tsplit_kernel<<<dim3(C_DIM / 32, C_DIM / 32), 256>>>(fc1_w,  fc1_la,  fc1_lb,  w1_hi,  w1_lo,  C_DIM);
    fold_tsplit_kernel<<<dim3(C_DIM / 32, C_DIM / 32), 256>>>(fc2_w,  fc2_la,  fc2_lb,  w2_hi,  w2_lo,  C_DIM);
    fold_tsplit_kernel<<<dim3(C_DIM / 32, C_DIM / 32), 256>>>(proj_w, proj_la, proj_lb, wp_hi,  wp_lo,  C_DIM);

    // 2) split x
    split_kernel<<<TOKENS * C_DIM / 256, 256>>>(x, xhi, xlo);

    // 3) qkv = x @ Wqkv  (bf16 hi/lo out)
    gemm_mma_kernel<<<dim3(N3C / 128, TOKENS / 128), 256, GEMM_SMEM>>>(
        xhi, xlo, wqkv_hi, wqkv_lo, nullptr, nullptr, nullptr, qkvhi, qkvlo, N3C, 0);

    // 4) HMMA flash attention -> xo (fp32 + bf16 splits)
    attention_mma_kernel<<<dim3(SEQ / 64, HEADS, BATCH), 128, ATT_SMEM>>>(
        qkvhi, qkvlo, maskc, xo, xohi, xolo);

    // 5) h = gelu(xo @ W1 + b1) -> bf16 splits only
    gemm_mma_kernel<<<dim3(C_DIM / 128, TOKENS / 128), 256, GEMM_SMEM>>>(
        xohi, xolo, w1_hi, w1_lo, fc1_b, nullptr, nullptr, hhi, hlo, C_DIM, 1);

    // 6) y = xo + (h @ W2 + b2) -> bf16 splits only
    gemm_mma_kernel<<<dim3(C_DIM / 128, TOKENS / 128), 256, GEMM_SMEM>>>(
        hhi, hlo, w2_hi, w2_lo, fc2_b, xo, nullptr, yhi, ylo, C_DIM, 0);

    // 7) out = y @ Wp + bp  (fp32 out)
    gemm_mma_kernel<<<dim3(C_DIM / 128, TOKENS / 128), 256, GEMM_SMEM>>>(
        yhi, ylo, wp_hi, wp_lo, proj_b, nullptr, (float*)d_out, nullptr, nullptr, C_DIM, 0);
}